// round 3
// baseline (speedup 1.0000x reference)
#include <cuda_runtime.h>

// Problem constants (fixed by the dataset)
#define BATCH 256
#define NNODE 2048
#define NROOT 64
#define DIM   64
#define KIN   2
#define NTYPE 8
#define HID   128   // 2*DIM
#define INW   128   // KIN*DIM

// One CTA per graph. 128 threads. Sequential over node positions; each node:
//   gather x[128] = concat(parent0, parent1)           (smem)
//   h = gelu(x @ W1[t] + b1[t])   (1x128 @ 128x128)    (smem)
//   out = h @ W2[t] + b2[t]       (1x128 @ 128x64)     -> global buf
// Thread layout for GEMVs: g = tid>>5 (i-range split, 4 groups), l = tid&31
// (column block). W1 read as float4 (coalesced 512B/warp), W2 as float2.
__global__ __launch_bounds__(128, 2)
void dag_seq_kernel(const float* __restrict__ root,
                    const float* __restrict__ W1,
                    const float* __restrict__ b1,
                    const float* __restrict__ W2,
                    const float* __restrict__ b2,
                    const int* __restrict__ idx,
                    const int* __restrict__ typ,
                    float* __restrict__ buf)
{
    const int b   = blockIdx.x;
    const int tid = threadIdx.x;
    float* mybuf = buf + (size_t)b * NNODE * DIM;

    // Copy root embeddings into buf[b, 0:64, :]  (4096 floats, float4-vectorized)
    {
        const float4* r4 = (const float4*)(root + (size_t)b * NROOT * DIM);
        float4* o4 = (float4*)mybuf;
        #pragma unroll
        for (int i = tid; i < NROOT * DIM / 4; i += 128) o4[i] = r4[i];
    }

    __shared__ float  xsh[INW];
    __shared__ float  hsh[HID];
    __shared__ float4 p1[4][32];   // gemv1 partials: [g][l] -> cols 4l..4l+3
    __shared__ float2 p2[4][32];   // gemv2 partials: [g][l] -> cols 2l..2l+1

    const int* myidx = idx + (size_t)b * NNODE * KIN;
    const int* mytyp = typ + (size_t)b * NNODE;

    const int g = tid >> 5;   // 0..3
    const int l = tid & 31;   // 0..31

    __syncthreads();

    for (int pos = NROOT; pos < NNODE; ++pos) {
        const int t = __ldg(mytyp + pos);

        // ---- gather parents into xsh: warp-coalesced (one parent row per 64 lanes)
        {
            const int k      = tid >> 6;               // which parent
            const int d      = tid & 63;               // embed dim
            const int parent = __ldg(myidx + pos * KIN + k);
            xsh[tid] = mybuf[(size_t)parent * DIM + d];
        }
        __syncthreads();

        // ---- GEMV1: h_partial = x[32g:32g+32] @ W1[t][.., 4l:4l+4]
        const float4* w1v = (const float4*)(W1 + (size_t)t * INW * HID);
        float4 acc = make_float4(0.f, 0.f, 0.f, 0.f);
        #pragma unroll 8
        for (int i = 0; i < 32; ++i) {
            const int ii  = (g << 5) + i;
            const float xv = xsh[ii];
            const float4 w = w1v[ii * 32 + l];   // row ii, cols 4l..4l+3
            acc.x = fmaf(xv, w.x, acc.x);
            acc.y = fmaf(xv, w.y, acc.y);
            acc.z = fmaf(xv, w.z, acc.z);
            acc.w = fmaf(xv, w.w, acc.w);
        }
        p1[g][l] = acc;
        __syncthreads();

        // ---- combine partials + bias + exact GELU; thread 'tid' owns hidden col tid
        {
            float s = __ldg(b1 + t * HID + tid);
            #pragma unroll
            for (int gg = 0; gg < 4; ++gg) {
                const float* pf = (const float*)&p1[gg][0];  // 128 contiguous floats
                s += pf[tid];
            }
            const float hv = 0.5f * s * (1.0f + erff(s * 0.70710678118654752f));
            hsh[tid] = hv;
        }
        __syncthreads();

        // ---- GEMV2: out_partial = h[32g:32g+32] @ W2[t][.., 2l:2l+2]
        const float2* w2v = (const float2*)(W2 + (size_t)t * HID * DIM);
        float2 acc2 = make_float2(0.f, 0.f);
        #pragma unroll 8
        for (int j = 0; j < 32; ++j) {
            const int jj   = (g << 5) + j;
            const float hv = hsh[jj];
            const float2 w = w2v[jj * 32 + l];   // row jj, cols 2l..2l+1
            acc2.x = fmaf(hv, w.x, acc2.x);
            acc2.y = fmaf(hv, w.y, acc2.y);
        }
        p2[g][l] = acc2;
        __syncthreads();

        // ---- reduce + bias, write to buf[b, pos, :]
        if (tid < DIM) {
            float o = __ldg(b2 + t * DIM + tid);
            #pragma unroll
            for (int gg = 0; gg < 4; ++gg) {
                const float* pf = (const float*)&p2[gg][0];  // 64 contiguous floats
                o += pf[tid];
            }
            mybuf[(size_t)pos * DIM + tid] = o;
        }
        __syncthreads();   // global write visible block-wide before next gather
    }
}

extern "C" void kernel_launch(void* const* d_in, const int* in_sizes, int n_in,
                              void* d_out, int out_size)
{
    const float* root = (const float*)d_in[0];   // [B, R, D]
    const float* W1   = (const float*)d_in[1];   // [T, 128, 128]
    const float* b1   = (const float*)d_in[2];   // [T, 128]
    const float* W2   = (const float*)d_in[3];   // [T, 128, 64]
    const float* b2   = (const float*)d_in[4];   // [T, 64]
    const int*   idx  = (const int*)d_in[5];     // [B, N, K]
    const int*   typ  = (const int*)d_in[6];     // [B, N]
    float* out = (float*)d_out;                  // [B, N, D]

    dag_seq_kernel<<<BATCH, 128>>>(root, W1, b1, W2, b2, idx, typ, out);
}

// round 5
// speedup vs baseline: 3.6363x; 3.6363x over previous
#include <cuda_runtime.h>
#include <math.h>

#define B     256
#define N     2048
#define RROOT 64
#define D     64
#define T     8
#define HID   128
#define INW   128

#define LMAX  256          // max levels supported (actual ~50)
#define G     64           // nodes per compute group (type-pure)
#define NITEMS (B*(N-RROOT))           // 507904
#define MAXG  16384
#define NCTA  148          // persistent grid: 1 CTA/SM, <= 152 SMs on GB300

// ---------------- scratch (static device globals; no allocation) ----------
__device__ unsigned short g_lev[B * N];
__device__ int d_counts[LMAX * T];
__device__ int d_cursor[LMAX * T];
__device__ int d_itemOff[LMAX * T];
__device__ int d_items[NITEMS];
__device__ int d_grpItemOff[MAXG];
__device__ int d_grpMeta[MAXG];        // type | (count<<8)
__device__ int d_grpOff[LMAX + 1];
__device__ int d_maxLev;
__device__ unsigned int d_barrier;

// ---------------- K0: reset control state (every replay) ------------------
__global__ void k_init()
{
    int tid = threadIdx.x;
    for (int i = tid; i < LMAX * T; i += blockDim.x) { d_counts[i] = 0; d_cursor[i] = 0; }
    if (tid == 0) { d_maxLev = 0; d_barrier = 0u; }
}

// ---------------- K1: per-graph levelization + (level,type) histogram -----
// one warp per graph; batch of 32 nodes, intra-batch deps resolved by shfl.
__global__ void k_levelize(const int* __restrict__ idx, const int* __restrict__ typ)
{
    const int b = blockIdx.x;
    const int lane = threadIdx.x;          // blockDim = 32
    __shared__ unsigned short lev_sm[N];   // 4KB
    __shared__ int hist[LMAX * T];         // 8KB

    for (int i = lane; i < LMAX * T; i += 32) hist[i] = 0;
    for (int i = lane; i < RROOT; i += 32) lev_sm[i] = 0;
    __syncwarp();

    const int2* idx2 = (const int2*)idx;   // [B][N] pairs
    int mymax = 0;

    for (int p0 = RROOT; p0 < N; p0 += 32) {
        const int i = p0 + lane;
        const int2 pp = idx2[b * N + i];
        const int pa = pp.x, pb = pp.y;
        // parents already finalized (previous batches)
        int la = (pa < p0) ? (int)lev_sm[pa] : 0;
        int lb = (pb < p0) ? (int)lev_sm[pb] : 0;
        int myl = max(la, lb) + 1;
        // resolve in-batch parents: lane j final before iteration j
        #pragma unroll
        for (int j = 0; j < 31; j++) {
            int lj = __shfl_sync(0xffffffffu, myl, j);
            if (pa == p0 + j) myl = max(myl, lj + 1);
            if (pb == p0 + j) myl = max(myl, lj + 1);
        }
        lev_sm[i] = (unsigned short)myl;
        mymax = max(mymax, myl);
        const int t = typ[b * N + i];
        atomicAdd(&hist[myl * T + t], 1);
        __syncwarp();
    }

    for (int i = lane; i < N; i += 32) g_lev[b * N + i] = lev_sm[i];
    for (int s = lane; s < LMAX * T; s += 32)
        if (hist[s]) atomicAdd(&d_counts[s], hist[s]);

    #pragma unroll
    for (int o = 16; o; o >>= 1) mymax = max(mymax, __shfl_xor_sync(0xffffffffu, mymax, o));
    if (lane == 0) atomicMax(&d_maxLev, mymax);
}

// ---------------- K2: segment offsets + padded group descriptors ----------
__global__ void k_segments()
{
    __shared__ int sCnt[LMAX * T];
    __shared__ int sOff[LMAX * T];
    __shared__ int sGrp[LMAX * T + 1];
    const int tid = threadIdx.x;

    for (int s = tid; s < LMAX * T; s += blockDim.x) sCnt[s] = d_counts[s];
    __syncthreads();

    if (tid == 0) {
        int acc = 0, gacc = 0;
        for (int s = 0; s < LMAX * T; s++) {
            sOff[s] = acc;  acc  += sCnt[s];
            sGrp[s] = gacc; gacc += (sCnt[s] + G - 1) / G;
        }
        sGrp[LMAX * T] = gacc;
    }
    __syncthreads();

    for (int s = tid; s < LMAX * T; s += blockDim.x) {
        d_itemOff[s] = sOff[s];
        int c = sCnt[s], off = sOff[s], gb = sGrp[s];
        int k = 0;
        while (c > 0) {
            const int take = (c < G) ? c : G;
            d_grpItemOff[gb + k] = off;
            d_grpMeta[gb + k]    = (s & (T - 1)) | (take << 8);
            off += take; c -= take; k++;
        }
    }
    for (int L = tid; L < LMAX; L += blockDim.x) d_grpOff[L] = sGrp[L * T];
    if (tid == 0) d_grpOff[LMAX] = sGrp[LMAX * T];
}

// ---------------- K3: scatter items + copy roots into out -----------------
__global__ void k_scatter(const float* __restrict__ root,
                          const int* __restrict__ typ,
                          float* __restrict__ buf)
{
    const int b = blockIdx.x;
    const int tid = threadIdx.x;

    // roots -> buf[b, 0:R, :]
    const float4* r4 = (const float4*)(root + (size_t)b * RROOT * D);
    float4* o4 = (float4*)(buf + (size_t)b * N * D);
    for (int i = tid; i < RROOT * D / 4; i += blockDim.x) o4[i] = r4[i];

    for (int i = RROOT + tid; i < N; i += blockDim.x) {
        const int lv = (int)g_lev[b * N + i];
        const int t  = typ[b * N + i];
        const int s  = lv * T + t;
        const int p  = atomicAdd(&d_cursor[s], 1);
        d_items[d_itemOff[s] + p] = (b << 11) | i;   // row index in buf
    }
}

// ---------------- K4: persistent level-synchronous compute ----------------
#define XSTRIDE 68
// dynamic smem layout (floats)
#define W1S_OFF 0                    // 128x128
#define W2S_OFF (W1S_OFF + 16384)    // 128x64
#define B1_OFF  (W2S_OFF + 8192)     // 128
#define B2_OFF  (B1_OFF + 128)       // 64
#define XT_OFF  (B2_OFF + 64)        // [k=128][XSTRIDE]
#define HT_OFF  (XT_OFF + 128*XSTRIDE)
#define IT_OFF  (HT_OFF + 128*XSTRIDE)   // 64 ints
#define SMEM_FLOATS (IT_OFF + 64)
#define SMEM_BYTES  (SMEM_FLOATS * 4)

__device__ __forceinline__ float gelu_exact(float v)
{
    return 0.5f * v * (1.0f + erff(v * 0.70710678118654752f));
}

__global__ __launch_bounds__(256, 1)
void k_compute(const float* __restrict__ W1, const float* __restrict__ b1,
               const float* __restrict__ W2, const float* __restrict__ b2,
               const int* __restrict__ idx,
               float* __restrict__ buf)
{
    extern __shared__ float sm[];
    int* items_sm = (int*)&sm[IT_OFF];

    const int tid = threadIdx.x;
    const int mg  = tid >> 5;          // GEMM1: 8 row-groups of 8
    const int ng  = tid & 31;          // GEMM1: 32 col-groups of 4
    const int mg2 = tid >> 4;          // GEMM2: 16 row-groups of 4
    const int ng2 = tid & 15;          // GEMM2: 16 col-groups of 4

    const int maxLev = d_maxLev;
    const int2* idx2 = (const int2*)idx;
    int prevType = -1;

    for (int L = 1; L <= maxLev; L++) {
        const int g0 = d_grpOff[L], g1 = d_grpOff[L + 1];

        for (int g = g0 + blockIdx.x; g < g1; g += gridDim.x) {
            const int meta = d_grpMeta[g];
            const int t = meta & 255;
            const int n = meta >> 8;
            const int ioff = d_grpItemOff[g];

            if (t != prevType) {
                const float4* w1g = (const float4*)(W1 + (size_t)t * INW * HID);
                const float4* w2g = (const float4*)(W2 + (size_t)t * HID * D);
                float4* w1s = (float4*)&sm[W1S_OFF];
                float4* w2s = (float4*)&sm[W2S_OFF];
                for (int j = tid; j < 4096; j += 256) w1s[j] = w1g[j];
                for (int j = tid; j < 2048; j += 256) w2s[j] = w2g[j];
                if (tid < HID) sm[B1_OFF + tid] = b1[t * HID + tid];
                if (tid < D)   sm[B2_OFF + tid] = b2[t * D + tid];
                prevType = t;
            }
            if (tid < G) items_sm[tid] = (tid < n) ? d_items[ioff + tid] : -1;
            __syncthreads();

            // ---- gather x (transposed): 4 threads per item
            {
                const int m = tid >> 2, q = tid & 3;
                const int it = items_sm[m];
                if (it >= 0) {
                    const int2 pp = idx2[it];           // it == b*2048 + i
                    const int par = (q >> 1) ? pp.y : pp.x;
                    const int browbase = it & ~2047;    // b*2048
                    const float4* src =
                        (const float4*)(buf + ((size_t)(browbase + par)) * D) + (q & 1) * 8;
                    const int kbase = (q >> 1) * 64 + (q & 1) * 32;
                    #pragma unroll
                    for (int e = 0; e < 8; e++) {
                        const float4 v = src[e];
                        const int k = kbase + e * 4;
                        sm[XT_OFF + (k + 0) * XSTRIDE + m] = v.x;
                        sm[XT_OFF + (k + 1) * XSTRIDE + m] = v.y;
                        sm[XT_OFF + (k + 2) * XSTRIDE + m] = v.z;
                        sm[XT_OFF + (k + 3) * XSTRIDE + m] = v.w;
                    }
                }
            }
            __syncthreads();

            // ---- GEMM1: [64 x 128] = x^T W1 ; thread tile M8 x N4
            {
                float acc[8][4];
                #pragma unroll
                for (int r = 0; r < 8; r++)
                    #pragma unroll
                    for (int c = 0; c < 4; c++) acc[r][c] = 0.f;

                const float* xbase = &sm[XT_OFF + mg * 8];
                const float* wbase = &sm[W1S_OFF + ng * 4];
                #pragma unroll 4
                for (int k = 0; k < 128; k++) {
                    const float4 xa = *(const float4*)(xbase + k * XSTRIDE);
                    const float4 xb = *(const float4*)(xbase + k * XSTRIDE + 4);
                    const float4 w  = *(const float4*)(wbase + k * HID);
                    const float xr[8] = { xa.x, xa.y, xa.z, xa.w, xb.x, xb.y, xb.z, xb.w };
                    const float wr[4] = { w.x, w.y, w.z, w.w };
                    #pragma unroll
                    for (int r = 0; r < 8; r++)
                        #pragma unroll
                        for (int c = 0; c < 4; c++)
                            acc[r][c] = fmaf(xr[r], wr[c], acc[r][c]);
                }
                // bias + GELU -> hT[col][m]
                #pragma unroll
                for (int c = 0; c < 4; c++) {
                    const int col = ng * 4 + c;
                    const float bb = sm[B1_OFF + col];
                    float4 lo, hi;
                    lo.x = gelu_exact(acc[0][c] + bb);
                    lo.y = gelu_exact(acc[1][c] + bb);
                    lo.z = gelu_exact(acc[2][c] + bb);
                    lo.w = gelu_exact(acc[3][c] + bb);
                    hi.x = gelu_exact(acc[4][c] + bb);
                    hi.y = gelu_exact(acc[5][c] + bb);
                    hi.z = gelu_exact(acc[6][c] + bb);
                    hi.w = gelu_exact(acc[7][c] + bb);
                    *(float4*)&sm[HT_OFF + col * XSTRIDE + mg * 8]     = lo;
                    *(float4*)&sm[HT_OFF + col * XSTRIDE + mg * 8 + 4] = hi;
                }
            }
            __syncthreads();

            // ---- GEMM2: [64 x 64] = h W2 ; thread tile M4 x N4 ; scatter out
            {
                float acc2[4][4];
                #pragma unroll
                for (int r = 0; r < 4; r++)
                    #pragma unroll
                    for (int c = 0; c < 4; c++) acc2[r][c] = 0.f;

                const float* hbase = &sm[HT_OFF + mg2 * 4];
                const float* wbase = &sm[W2S_OFF + ng2 * 4];
                #pragma unroll 4
                for (int k = 0; k < 128; k++) {
                    const float4 h = *(const float4*)(hbase + k * XSTRIDE);
                    const float4 w = *(const float4*)(wbase + k * D);
                    const float hr[4] = { h.x, h.y, h.z, h.w };
                    const float wr[4] = { w.x, w.y, w.z, w.w };
                    #pragma unroll
                    for (int r = 0; r < 4; r++)
                        #pragma unroll
                        for (int c = 0; c < 4; c++)
                            acc2[r][c] = fmaf(hr[r], wr[c], acc2[r][c]);
                }
                const float4 bb = *(const float4*)&sm[B2_OFF + ng2 * 4];
                #pragma unroll
                for (int r = 0; r < 4; r++) {
                    const int m = mg2 * 4 + r;
                    const int it = items_sm[m];
                    if (it >= 0) {
                        float4 o;
                        o.x = acc2[r][0] + bb.x;
                        o.y = acc2[r][1] + bb.y;
                        o.z = acc2[r][2] + bb.z;
                        o.w = acc2[r][3] + bb.w;
                        *(float4*)&buf[(size_t)it * D + ng2 * 4] = o;
                    }
                }
            }
            __syncthreads();   // smem reuse for next group
        }

        // ---- grid barrier (all NCTA CTAs are co-resident: 1 CTA/SM)
        __syncthreads();
        if (tid == 0) {
            __threadfence();                       // release buf writes
            atomicAdd(&d_barrier, 1u);
            const unsigned target = (unsigned)gridDim.x * (unsigned)L;
            while (*(volatile unsigned*)&d_barrier < target) { }
            __threadfence();                       // acquire
        }
        __syncthreads();
    }
}

// ---------------- host launcher -------------------------------------------
extern "C" void kernel_launch(void* const* d_in, const int* in_sizes, int n_in,
                              void* d_out, int out_size)
{
    const float* root = (const float*)d_in[0];   // [B, R, D]
    const float* W1   = (const float*)d_in[1];   // [T, 128, 128]
    const float* b1   = (const float*)d_in[2];   // [T, 128]
    const float* W2   = (const float*)d_in[3];   // [T, 128, 64]
    const float* b2   = (const float*)d_in[4];   // [T, 64]
    const int*   idx  = (const int*)d_in[5];     // [B, N, 2]
    const int*   typ  = (const int*)d_in[6];     // [B, N]
    float* out = (float*)d_out;                  // [B, N, D]

    static int configured = 0;
    if (!configured) {
        cudaFuncSetAttribute(k_compute, cudaFuncAttributeMaxDynamicSharedMemorySize, SMEM_BYTES);
        configured = 1;
    }

    k_init<<<1, 256>>>();
    k_levelize<<<B, 32>>>(idx, typ);
    k_segments<<<1, 256>>>();
    k_scatter<<<B, 256>>>(root, typ, out);
    k_compute<<<NCTA, 256, SMEM_BYTES>>>(W1, b1, W2, b2, idx, out);
}

// round 7
// speedup vs baseline: 3.8276x; 1.0526x over previous
#include <cuda_runtime.h>
#include <math.h>

#define B     256
#define N     2048
#define RROOT 64
#define D     64
#define T     8
#define HID   128
#define INW   128

#define LMAX  256          // max levels supported (actual ~50)
#define G     64           // nodes per compute group (type-pure)
#define NITEMS (B*(N-RROOT))           // 507904
#define MAXG  16384
#define NCTA  148          // persistent grid: 1 CTA/SM co-resident

// ---------------- scratch (static device globals; no allocation) ----------
__device__ unsigned short g_lev[B * N];
__device__ int d_counts[LMAX * T];
__device__ int d_cursor[LMAX * T];
__device__ int d_itemOff[LMAX * T];
__device__ int d_items[NITEMS];
__device__ int d_grpItemOff[MAXG];
__device__ int d_grpMeta[MAXG];        // type | (count<<8)
__device__ int d_totalG;
__device__ int d_done[B * N];          // per-node completion flags
__device__ int d_qhead;                // global group queue head

// ---------------- K0: reset control state (every replay) ------------------
__global__ void k_init()
{
    const int i = blockIdx.x * blockDim.x + threadIdx.x;
    const int stride = gridDim.x * blockDim.x;
    for (int j = i; j < B * N; j += stride) d_done[j] = 0;
    for (int j = i; j < LMAX * T; j += stride) { d_counts[j] = 0; d_cursor[j] = 0; }
    if (i == 0) d_qhead = 0;
}

// ---------------- K1: per-graph levelization + (level,type) histogram -----
__global__ void k_levelize(const int* __restrict__ idx, const int* __restrict__ typ)
{
    const int b = blockIdx.x;
    const int lane = threadIdx.x;          // blockDim = 32
    __shared__ unsigned short lev_sm[N];
    __shared__ int hist[LMAX * T];

    for (int i = lane; i < LMAX * T; i += 32) hist[i] = 0;
    for (int i = lane; i < RROOT; i += 32) lev_sm[i] = 0;
    __syncwarp();

    const int2* idx2 = (const int2*)idx;

    for (int p0 = RROOT; p0 < N; p0 += 32) {
        const int i = p0 + lane;
        const int2 pp = idx2[b * N + i];
        const int pa = pp.x, pb = pp.y;
        int la = (pa < p0) ? (int)lev_sm[pa] : 0;
        int lb = (pb < p0) ? (int)lev_sm[pb] : 0;
        int myl = max(la, lb) + 1;
        #pragma unroll
        for (int j = 0; j < 31; j++) {
            int lj = __shfl_sync(0xffffffffu, myl, j);
            if (pa == p0 + j) myl = max(myl, lj + 1);
            if (pb == p0 + j) myl = max(myl, lj + 1);
        }
        lev_sm[i] = (unsigned short)myl;
        const int t = typ[b * N + i];
        atomicAdd(&hist[myl * T + t], 1);
        __syncwarp();
    }

    for (int i = lane; i < N; i += 32) g_lev[b * N + i] = lev_sm[i];
    for (int s = lane; s < LMAX * T; s += 32)
        if (hist[s]) atomicAdd(&d_counts[s], hist[s]);
}

// ---------------- K2: parallel scan -> offsets + group descriptors --------
// scan (itemCount, groupCount) packed in one u64: low32 items, high32 groups
__global__ void k_segments()
{
    const int tid  = threadIdx.x;          // 256
    const int lane = tid & 31;
    const int wid  = tid >> 5;
    const int base = tid * 8;

    unsigned long long locPre[8];
    int cnts[8];
    unsigned long long run = 0;
    #pragma unroll
    for (int j = 0; j < 8; j++) {
        const int c = d_counts[base + j];
        cnts[j] = c;
        locPre[j] = run;
        run += (((unsigned long long)((c + G - 1) / G)) << 32) | (unsigned)c;
    }

    unsigned long long x = run;
    #pragma unroll
    for (int o = 1; o < 32; o <<= 1) {
        unsigned long long y = __shfl_up_sync(0xffffffffu, x, o);
        if (lane >= o) x += y;
    }
    __shared__ unsigned long long wsum[8];
    if (lane == 31) wsum[wid] = x;
    __syncthreads();
    if (tid < 8) {
        unsigned long long w = wsum[tid];
        #pragma unroll
        for (int o = 1; o < 8; o <<= 1) {
            unsigned long long y = __shfl_up_sync(0xffu, w, o, 8);
            if (tid >= o) w += y;
        }
        wsum[tid] = w;
    }
    __syncthreads();
    unsigned long long excl = x - run + (wid ? wsum[wid - 1] : 0ull);

    if (tid == 255) d_totalG = (int)((excl + run) >> 32);

    #pragma unroll
    for (int j = 0; j < 8; j++) {
        const unsigned long long e = excl + locPre[j];
        int off = (int)(e & 0xffffffffull);
        int gb  = (int)(e >> 32);
        const int s = base + j;
        d_itemOff[s] = off;
        int c = cnts[j];
        while (c > 0) {
            const int take = (c < G) ? c : G;
            d_grpItemOff[gb] = off;
            d_grpMeta[gb]    = (s & (T - 1)) | (take << 8);
            off += take; c -= take; gb++;
        }
    }
}

// ---------------- K3: scatter items (smem-aggregated atomics) + roots -----
__global__ void k_scatter(const float* __restrict__ root,
                          const int* __restrict__ typ,
                          float* __restrict__ buf)
{
    const int b = blockIdx.x;
    const int tid = threadIdx.x;           // 256
    __shared__ int hist[LMAX * T];         // 8KB
    __shared__ int basec[LMAX * T];        // 8KB
    __shared__ unsigned short ssm[N];      // 4KB

    for (int s = tid; s < LMAX * T; s += 256) hist[s] = 0;

    // roots -> buf[b, 0:R, :]
    const float4* r4 = (const float4*)(root + (size_t)b * RROOT * D);
    float4* o4 = (float4*)(buf + (size_t)b * N * D);
    for (int i = tid; i < RROOT * D / 4; i += 256) o4[i] = r4[i];
    __syncthreads();

    for (int i = RROOT + tid; i < N; i += 256) {
        const int s = (int)g_lev[b * N + i] * T + typ[b * N + i];
        ssm[i] = (unsigned short)s;
        atomicAdd(&hist[s], 1);
    }
    __syncthreads();

    for (int s = tid; s < LMAX * T; s += 256)
        if (hist[s]) basec[s] = atomicAdd(&d_cursor[s], hist[s]);
    __syncthreads();

    for (int i = RROOT + tid; i < N; i += 256) {
        const int s = (int)ssm[i];
        const int p = atomicAdd(&basec[s], 1);
        d_items[d_itemOff[s] + p] = (b << 11) | i;
    }
}

// ---------------- K4: persistent queue-driven dataflow compute ------------
#define XSTRIDE 68
#define W1S_OFF 0                        // 128x128
#define W2S_OFF (W1S_OFF + 16384)        // 128x64
#define B1_OFF  (W2S_OFF + 8192)         // 128
#define B2_OFF  (B1_OFF + 128)           // 64
#define XT_OFF  (B2_OFF + 64)            // [k=128][XSTRIDE]
#define HT_OFF  (XT_OFF + 128*XSTRIDE)
#define IT_OFF  (HT_OFF + 128*XSTRIDE)   // 64 ints
#define SMEM_FLOATS (IT_OFF + 64)
#define SMEM_BYTES  (SMEM_FLOATS * 4)

__device__ __forceinline__ float gelu_exact(float v)
{
    return 0.5f * v * (1.0f + erff(v * 0.70710678118654752f));
}

// packed fp32x2 helpers (SASS FFMA2 — 2x fp32 FMA rate, bit-identical per lane)
__device__ __forceinline__ void ffma2(unsigned long long& d,
                                      unsigned long long a, unsigned long long bv)
{
    asm("fma.rn.f32x2 %0, %1, %2, %0;" : "+l"(d) : "l"(a), "l"(bv));
}
__device__ __forceinline__ unsigned long long splat2(float f)
{
    unsigned long long r;
    asm("mov.b64 %0, {%1, %1};" : "=l"(r) : "f"(f));
    return r;
}
__device__ __forceinline__ float2 unpack2(unsigned long long v)
{
    float2 p;
    asm("mov.b64 {%0, %1}, %2;" : "=f"(p.x), "=f"(p.y) : "l"(v));
    return p;
}
// L2-coherent vector load (cross-SM producer/consumer)
__device__ __forceinline__ float4 ldcg4(const float* p)
{
    float4 v;
    asm volatile("ld.global.cg.v4.f32 {%0,%1,%2,%3}, [%4];"
                 : "=f"(v.x), "=f"(v.y), "=f"(v.z), "=f"(v.w) : "l"(p));
    return v;
}

__global__ __launch_bounds__(256, 1)
void k_compute(const float* __restrict__ W1, const float* __restrict__ b1,
               const float* __restrict__ W2, const float* __restrict__ b2,
               const int* __restrict__ idx,
               float* __restrict__ buf)
{
    extern __shared__ float sm[];
    int* items_sm = (int*)&sm[IT_OFF];
    __shared__ int gq;

    const int tid = threadIdx.x;
    const int mg  = tid >> 5;          // GEMM1: 8 row-groups of 8
    const int ng  = tid & 31;          // GEMM1: 32 col-groups of 4
    const int mg2 = tid >> 4;          // GEMM2: 16 row-groups of 4
    const int ng2 = tid & 15;          // GEMM2: 16 col-groups of 4

    const int totalG = d_totalG;
    const int2* idx2 = (const int2*)idx;
    int prevType = -1;

    for (;;) {
        if (tid == 0) gq = atomicAdd(&d_qhead, 1);
        __syncthreads();
        const int g = gq;
        if (g >= totalG) break;

        const int meta = d_grpMeta[g];
        const int t = meta & 255;
        const int n = meta >> 8;
        const int ioff = d_grpItemOff[g];

        if (t != prevType) {
            const float4* w1g = (const float4*)(W1 + (size_t)t * INW * HID);
            const float4* w2g = (const float4*)(W2 + (size_t)t * HID * D);
            float4* w1s = (float4*)&sm[W1S_OFF];
            float4* w2s = (float4*)&sm[W2S_OFF];
            for (int j = tid; j < 4096; j += 256) w1s[j] = w1g[j];
            for (int j = tid; j < 2048; j += 256) w2s[j] = w2g[j];
            if (tid < HID) sm[B1_OFF + tid] = b1[t * HID + tid];
            if (tid < D)   sm[B2_OFF + tid] = b2[t * D + tid];
            prevType = t;
        }
        if (tid < G) items_sm[tid] = (tid < n) ? d_items[ioff + tid] : -1;
        __syncthreads();

        // ---- wait for this group's parents (dataflow; no grid barrier)
        if (tid < 2 * G) {
            const int it = items_sm[tid >> 1];
            if (it >= 0) {
                const int2 pp = idx2[it];
                const int par = (tid & 1) ? pp.y : pp.x;
                if (par >= RROOT) {
                    volatile int* f = &d_done[(it & ~(N - 1)) | par];
                    while (*f == 0) __nanosleep(32);
                }
            }
        }
        __syncthreads();

        // ---- gather x (transposed): 4 threads per item; L2-coherent loads
        {
            const int m = tid >> 2, q = tid & 3;
            const int it = items_sm[m];
            if (it >= 0) {
                const int2 pp = idx2[it];
                const int par = (q >> 1) ? pp.y : pp.x;
                const int browbase = it & ~(N - 1);
                const float* src = buf + ((size_t)(browbase + par)) * D + (q & 1) * 32;
                const int kbase = (q >> 1) * 64 + (q & 1) * 32;
                #pragma unroll
                for (int e = 0; e < 8; e++) {
                    const float4 v = ldcg4(src + e * 4);
                    const int k = kbase + e * 4;
                    sm[XT_OFF + (k + 0) * XSTRIDE + m] = v.x;
                    sm[XT_OFF + (k + 1) * XSTRIDE + m] = v.y;
                    sm[XT_OFF + (k + 2) * XSTRIDE + m] = v.z;
                    sm[XT_OFF + (k + 3) * XSTRIDE + m] = v.w;
                }
            }
        }
        __syncthreads();

        // ---- GEMM1: [64 x 128] = x^T W1 ; thread tile M8 x N4, packed f32x2
        {
            unsigned long long acc[4][4];   // [rowpair 01/23/45/67][col]
            #pragma unroll
            for (int r = 0; r < 4; r++)
                #pragma unroll
                for (int c = 0; c < 4; c++) acc[r][c] = 0ull;

            const float* xbase = &sm[XT_OFF + mg * 8];
            const float* wbase = &sm[W1S_OFF + ng * 4];
            #pragma unroll 4
            for (int k = 0; k < 128; k++) {
                const ulonglong2 xa = *(const ulonglong2*)(xbase + k * XSTRIDE);     // rows 0-3
                const ulonglong2 xb = *(const ulonglong2*)(xbase + k * XSTRIDE + 4); // rows 4-7
                const float4 w = *(const float4*)(wbase + k * HID);
                const unsigned long long w0 = splat2(w.x), w1 = splat2(w.y),
                                         w2 = splat2(w.z), w3 = splat2(w.w);
                ffma2(acc[0][0], xa.x, w0); ffma2(acc[0][1], xa.x, w1);
                ffma2(acc[0][2], xa.x, w2); ffma2(acc[0][3], xa.x, w3);
                ffma2(acc[1][0], xa.y, w0); ffma2(acc[1][1], xa.y, w1);
                ffma2(acc[1][2], xa.y, w2); ffma2(acc[1][3], xa.y, w3);
                ffma2(acc[2][0], xb.x, w0); ffma2(acc[2][1], xb.x, w1);
                ffma2(acc[2][2], xb.x, w2); ffma2(acc[2][3], xb.x, w3);
                ffma2(acc[3][0], xb.y, w0); ffma2(acc[3][1], xb.y, w1);
                ffma2(acc[3][2], xb.y, w2); ffma2(acc[3][3], xb.y, w3);
            }
            // bias + GELU -> hT[col][m]
            #pragma unroll
            for (int c = 0; c < 4; c++) {
                const int col = ng * 4 + c;
                const float bb = sm[B1_OFF + col];
                const float2 r01 = unpack2(acc[0][c]);
                const float2 r23 = unpack2(acc[1][c]);
                const float2 r45 = unpack2(acc[2][c]);
                const float2 r67 = unpack2(acc[3][c]);
                float4 lo, hi;
                lo.x = gelu_exact(r01.x + bb);
                lo.y = gelu_exact(r01.y + bb);
                lo.z = gelu_exact(r23.x + bb);
                lo.w = gelu_exact(r23.y + bb);
                hi.x = gelu_exact(r45.x + bb);
                hi.y = gelu_exact(r45.y + bb);
                hi.z = gelu_exact(r67.x + bb);
                hi.w = gelu_exact(r67.y + bb);
                *(float4*)&sm[HT_OFF + col * XSTRIDE + mg * 8]     = lo;
                *(float4*)&sm[HT_OFF + col * XSTRIDE + mg * 8 + 4] = hi;
            }
        }
        __syncthreads();

        // ---- GEMM2: [64 x 64] = h W2 ; thread tile M4 x N4, packed f32x2
        {
            unsigned long long acc2[2][4];  // [rowpair 01/23][col]
            #pragma unroll
            for (int r = 0; r < 2; r++)
                #pragma unroll
                for (int c = 0; c < 4; c++) acc2[r][c] = 0ull;

            const float* hbase = &sm[HT_OFF + mg2 * 4];
            const float* wbase = &sm[W2S_OFF + ng2 * 4];
            #pragma unroll 4
            for (int k = 0; k < 128; k++) {
                const ulonglong2 h = *(const ulonglong2*)(hbase + k * XSTRIDE); // rows 0-3
                const float4 w = *(const float4*)(wbase + k * D);
                const unsigned long long w0 = splat2(w.x), w1 = splat2(w.y),
                                         w2 = splat2(w.z), w3 = splat2(w.w);
                ffma2(acc2[0][0], h.x, w0); ffma2(acc2[0][1], h.x, w1);
                ffma2(acc2[0][2], h.x, w2); ffma2(acc2[0][3], h.x, w3);
                ffma2(acc2[1][0], h.y, w0); ffma2(acc2[1][1], h.y, w1);
                ffma2(acc2[1][2], h.y, w2); ffma2(acc2[1][3], h.y, w3);
            }
            const float4 bb = *(const float4*)&sm[B2_OFF + ng2 * 4];
            float o[4][4];
            #pragma unroll
            for (int c = 0; c < 4; c++) {
                const float bc = (c == 0) ? bb.x : (c == 1) ? bb.y : (c == 2) ? bb.z : bb.w;
                const float2 p0 = unpack2(acc2[0][c]);
                const float2 p1 = unpack2(acc2[1][c]);
                o[0][c] = p0.x + bc; o[1][c] = p0.y + bc;
                o[2][c] = p1.x + bc; o[3][c] = p1.y + bc;
            }
            #pragma unroll
            for (int r = 0; r < 4; r++) {
                const int m = mg2 * 4 + r;
                const int it = items_sm[m];
                if (it >= 0) {
                    float4 ov;
                    ov.x = o[r][0]; ov.y = o[r][1]; ov.z = o[r][2]; ov.w = o[r][3];
                    *(float4*)&buf[(size_t)it * D + ng2 * 4] = ov;
                }
            }
        }

        // ---- publish: buf writes -> fence -> flags (release)
        __threadfence();
        __syncthreads();
        if (tid < G) {
            const int it = items_sm[tid];
            if (it >= 0) *((volatile int*)&d_done[it]) = 1;
        }
        __syncthreads();   // smem reuse guard for next group
    }
}

// ---------------- host launcher -------------------------------------------
extern "C" void kernel_launch(void* const* d_in, const int* in_sizes, int n_in,
                              void* d_out, int out_size)
{
    const float* root = (const float*)d_in[0];   // [B, R, D]
    const float* W1   = (const float*)d_in[1];   // [T, 128, 128]
    const float* b1   = (const float*)d_in[2];   // [T, 128]
    const float* W2   = (const float*)d_in[3];   // [T, 128, 64]
    const float* b2   = (const float*)d_in[4];   // [T, 64]
    const int*   idx  = (const int*)d_in[5];     // [B, N, 2]
    const int*   typ  = (const int*)d_in[6];     // [B, N]
    float* out = (float*)d_out;                  // [B, N, D]

    static int configured = 0;
    if (!configured) {
        cudaFuncSetAttribute(k_compute, cudaFuncAttributeMaxDynamicSharedMemorySize, SMEM_BYTES);
        configured = 1;
    }

    k_init<<<256, 256>>>();
    k_levelize<<<B, 32>>>(idx, typ);
    k_segments<<<1, 256>>>();
    k_scatter<<<B, 256>>>(root, typ, out);
    k_compute<<<NCTA, 256, SMEM_BYTES>>>(W1, b1, W2, b2, idx, out);
}

// round 8
// speedup vs baseline: 4.0295x; 1.0528x over previous
#include <cuda_runtime.h>
#include <math.h>

#define B     256
#define N     2048
#define RROOT 64
#define D     64
#define T     8
#define HID   128
#define INW   128

#define LMAX  256          // max levels supported (actual ~50)
#define WMAX  96           // max nodes per compute group
#define NITEMS (B*(N-RROOT))
#define MAXG  16384
#define NCTA  148          // persistent grid: 1 CTA/SM co-resident

// ---------------- scratch (static device globals; no allocation) ----------
__device__ unsigned short g_lev[B * N];
__device__ int d_counts[LMAX * T];
__device__ int d_cursor[LMAX * T];
__device__ int d_itemOff[LMAX * T];
__device__ int d_items[NITEMS];
__device__ int d_grpItemOff[MAXG];
__device__ int d_grpMeta[MAXG];        // type | (count<<8)
__device__ int d_totalG;
__device__ int d_done[B * N];          // per-node completion flags
__device__ int d_qhead;                // global group queue head

// ---------------- K0: reset control state (every replay) ------------------
__global__ void k_init()
{
    const int i = blockIdx.x * blockDim.x + threadIdx.x;
    const int stride = gridDim.x * blockDim.x;
    for (int j = i; j < B * N; j += stride) d_done[j] = 0;
    for (int j = i; j < LMAX * T; j += stride) { d_counts[j] = 0; d_cursor[j] = 0; }
    if (i == 0) d_qhead = 0;
}

// ---------------- K1: per-graph levelization + (level,type) histogram -----
__global__ void k_levelize(const int* __restrict__ idx, const int* __restrict__ typ)
{
    const int b = blockIdx.x;
    const int lane = threadIdx.x;          // blockDim = 32
    __shared__ unsigned short lev_sm[N];
    __shared__ int hist[LMAX * T];

    for (int i = lane; i < LMAX * T; i += 32) hist[i] = 0;
    for (int i = lane; i < RROOT; i += 32) lev_sm[i] = 0;
    __syncwarp();

    const int2* idx2 = (const int2*)idx;

    for (int p0 = RROOT; p0 < N; p0 += 32) {
        const int i = p0 + lane;
        const int2 pp = idx2[b * N + i];
        const int pa = pp.x, pb = pp.y;
        int la = (pa < p0) ? (int)lev_sm[pa] : 0;
        int lb = (pb < p0) ? (int)lev_sm[pb] : 0;
        int myl = max(la, lb) + 1;
        #pragma unroll
        for (int j = 0; j < 31; j++) {
            int lj = __shfl_sync(0xffffffffu, myl, j);
            if (pa == p0 + j) myl = max(myl, lj + 1);
            if (pb == p0 + j) myl = max(myl, lj + 1);
        }
        lev_sm[i] = (unsigned short)myl;
        const int t = typ[b * N + i];
        atomicAdd(&hist[myl * T + t], 1);
        __syncwarp();
    }

    for (int i = lane; i < N; i += 32) g_lev[b * N + i] = lev_sm[i];
    for (int s = lane; s < LMAX * T; s += 32)
        if (hist[s]) atomicAdd(&d_counts[s], hist[s]);
}

// ---------------- K2: adaptive per-level group sizing ---------------------
// For each level: waves w = ceil(LT/(NCTA*WMAX)); group size G_L = ceil(LT/(NCTA*w));
// per-type group counts apportioned + trimmed so total <= NCTA*w when possible.
__global__ void k_segments()
{
    __shared__ int sCnt[LMAX * T];               // 8KB
    __shared__ unsigned char sNS[LMAX * T];      // 2KB
    __shared__ int levG[LMAX], levN[LMAX];
    __shared__ int levGoff[LMAX], levIoff[LMAX];
    const int tid = threadIdx.x;                 // 256

    for (int s = tid; s < LMAX * T; s += 256) sCnt[s] = d_counts[s];
    __syncthreads();

    if (tid < LMAX) {
        const int L = tid;
        int c[T]; int LT = 0;
        #pragma unroll
        for (int t = 0; t < T; t++) { c[t] = sCnt[L * T + t]; LT += c[t]; }
        int tot = 0;
        if (LT > 0) {
            const int w = (LT + NCTA * WMAX - 1) / (NCTA * WMAX);
            const int slots = NCTA * w;
            const int GL = (LT + slots - 1) / slots;       // <= WMAX
            int ns[T];
            #pragma unroll
            for (int t = 0; t < T; t++) { ns[t] = (c[t] + GL - 1) / GL; tot += ns[t]; }
            bool prog = true;
            while (tot > slots && prog) {
                prog = false;
                #pragma unroll
                for (int t = 0; t < T; t++)
                    if (tot > slots && ns[t] > 1 &&
                        (c[t] + ns[t] - 2) / (ns[t] - 1) <= WMAX) {
                        ns[t]--; tot--; prog = true;
                    }
            }
            #pragma unroll
            for (int t = 0; t < T; t++) sNS[L * T + t] = (unsigned char)ns[t];
        } else {
            #pragma unroll
            for (int t = 0; t < T; t++) sNS[L * T + t] = 0;
        }
        levG[L] = tot; levN[L] = LT;
    }
    __syncthreads();

    if (tid == 0) {
        int ga = 0, ia = 0;
        for (int L = 0; L < LMAX; L++) {
            levGoff[L] = ga; levIoff[L] = ia;
            ga += levG[L]; ia += levN[L];
        }
        d_totalG = ga;
    }
    __syncthreads();

    if (tid < LMAX) {
        const int L = tid;
        int gb = levGoff[L], off = levIoff[L];
        for (int t = 0; t < T; t++) {
            const int s = L * T + t;
            const int ct = sCnt[s];
            const int ns = (int)sNS[s];
            d_itemOff[s] = off;
            if (ns > 0) {
                const int base = ct / ns, rem = ct % ns;
                for (int k2 = 0; k2 < ns; k2++) {
                    const int take = base + (k2 < rem ? 1 : 0);
                    d_grpItemOff[gb] = off;
                    d_grpMeta[gb]    = t | (take << 8);
                    off += take; gb++;
                }
            }
        }
    }
}

// ---------------- K3: scatter items (smem-aggregated atomics) + roots -----
__global__ void k_scatter(const float* __restrict__ root,
                          const int* __restrict__ typ,
                          float* __restrict__ buf)
{
    const int b = blockIdx.x;
    const int tid = threadIdx.x;           // 256
    __shared__ int hist[LMAX * T];         // 8KB
    __shared__ int basec[LMAX * T];        // 8KB
    __shared__ unsigned short ssm[N];      // 4KB

    for (int s = tid; s < LMAX * T; s += 256) hist[s] = 0;

    const float4* r4 = (const float4*)(root + (size_t)b * RROOT * D);
    float4* o4 = (float4*)(buf + (size_t)b * N * D);
    for (int i = tid; i < RROOT * D / 4; i += 256) o4[i] = r4[i];
    __syncthreads();

    for (int i = RROOT + tid; i < N; i += 256) {
        const int s = (int)g_lev[b * N + i] * T + typ[b * N + i];
        ssm[i] = (unsigned short)s;
        atomicAdd(&hist[s], 1);
    }
    __syncthreads();

    for (int s = tid; s < LMAX * T; s += 256)
        if (hist[s]) basec[s] = atomicAdd(&d_cursor[s], hist[s]);
    __syncthreads();

    for (int i = RROOT + tid; i < N; i += 256) {
        const int s = (int)ssm[i];
        const int p = atomicAdd(&basec[s], 1);
        d_items[d_itemOff[s] + p] = (b << 11) | i;
    }
}

// ---------------- K4: persistent queue-driven dataflow compute ------------
// M up to 96 nodes per group. GEMM1 thread-tile M12xN4 (8x32 grid),
// GEMM2 thread-tile M6xN4 (16x16 grid). Warp-level row skip for partial groups.
#define XSTRIDE 100
#define W1S_OFF 0                         // 128x128
#define W2S_OFF (W1S_OFF + 16384)         // 128x64
#define B1_OFF  (W2S_OFF + 8192)          // 128
#define B2_OFF  (B1_OFF + 128)            // 64
#define XT_OFF  (B2_OFF + 64)             // [k=128][XSTRIDE]
#define HT_OFF  (XT_OFF + 128*XSTRIDE)    // [k=128][XSTRIDE]
#define IT_OFF  (HT_OFF + 128*XSTRIDE)    // WMAX ints
#define SMEM_FLOATS (IT_OFF + WMAX)
#define SMEM_BYTES  (SMEM_FLOATS * 4)

__device__ __forceinline__ float gelu_exact(float v)
{
    return 0.5f * v * (1.0f + erff(v * 0.70710678118654752f));
}
__device__ __forceinline__ void ffma2(unsigned long long& d,
                                      unsigned long long a, unsigned long long bv)
{
    asm("fma.rn.f32x2 %0, %1, %2, %0;" : "+l"(d) : "l"(a), "l"(bv));
}
__device__ __forceinline__ unsigned long long splat2(float f)
{
    unsigned long long r;
    asm("mov.b64 %0, {%1, %1};" : "=l"(r) : "f"(f));
    return r;
}
__device__ __forceinline__ float2 unpack2(unsigned long long v)
{
    float2 p;
    asm("mov.b64 {%0, %1}, %2;" : "=f"(p.x), "=f"(p.y) : "l"(v));
    return p;
}
__device__ __forceinline__ float4 ldcg4(const float* p)
{
    float4 v;
    asm volatile("ld.global.cg.v4.f32 {%0,%1,%2,%3}, [%4];"
                 : "=f"(v.x), "=f"(v.y), "=f"(v.z), "=f"(v.w) : "l"(p));
    return v;
}

__global__ __launch_bounds__(256, 1)
void k_compute(const float* __restrict__ W1, const float* __restrict__ b1,
               const float* __restrict__ W2, const float* __restrict__ b2,
               const int* __restrict__ idx,
               float* __restrict__ buf)
{
    extern __shared__ float sm[];
    int* items_sm = (int*)&sm[IT_OFF];
    __shared__ int gq;

    const int tid = threadIdx.x;
    const int mg  = tid >> 5;          // GEMM1: rows mg*12..+11
    const int ng  = tid & 31;          // GEMM1: cols ng*4..+3
    const int mg2 = tid >> 4;          // GEMM2: rows mg2*6..+5
    const int ng2 = tid & 15;          // GEMM2: cols ng2*4..+3

    const int totalG = d_totalG;
    const int2* idx2 = (const int2*)idx;
    int prevType = -1;

    for (;;) {
        if (tid == 0) gq = atomicAdd(&d_qhead, 1);
        __syncthreads();
        const int g = gq;
        if (g >= totalG) break;

        const int meta = d_grpMeta[g];
        const int t = meta & 255;
        const int n = meta >> 8;
        const int ioff = d_grpItemOff[g];

        if (t != prevType) {
            const float4* w1g = (const float4*)(W1 + (size_t)t * INW * HID);
            const float4* w2g = (const float4*)(W2 + (size_t)t * HID * D);
            float4* w1s = (float4*)&sm[W1S_OFF];
            float4* w2s = (float4*)&sm[W2S_OFF];
            for (int j = tid; j < 4096; j += 256) w1s[j] = w1g[j];
            for (int j = tid; j < 2048; j += 256) w2s[j] = w2g[j];
            if (tid < HID) sm[B1_OFF + tid] = b1[t * HID + tid];
            if (tid < D)   sm[B2_OFF + tid] = b2[t * D + tid];
            prevType = t;
        }
        if (tid < WMAX) items_sm[tid] = (tid < n) ? d_items[ioff + tid] : -1;
        __syncthreads();

        // ---- wait for this group's parents (dataflow; no grid barrier)
        if (tid < 2 * n) {
            const int it = items_sm[tid >> 1];
            const int2 pp = idx2[it];
            const int par = (tid & 1) ? pp.y : pp.x;
            if (par >= RROOT) {
                volatile int* f = &d_done[(it & ~(N - 1)) | par];
                while (*f == 0) __nanosleep(32);
            }
        }
        __syncthreads();

        // ---- gather x (transposed): 2 threads per item (one parent each)
        if (tid < 2 * n) {
            const int m = tid >> 1, q = tid & 1;
            const int it = items_sm[m];
            const int2 pp = idx2[it];
            const int par = q ? pp.y : pp.x;
            const int browbase = it & ~(N - 1);
            const float* src = buf + ((size_t)(browbase + par)) * D;
            const int kbase = q * 64;
            #pragma unroll
            for (int e = 0; e < 16; e++) {
                const float4 v = ldcg4(src + e * 4);
                const int k = kbase + e * 4;
                sm[XT_OFF + (k + 0) * XSTRIDE + m] = v.x;
                sm[XT_OFF + (k + 1) * XSTRIDE + m] = v.y;
                sm[XT_OFF + (k + 2) * XSTRIDE + m] = v.z;
                sm[XT_OFF + (k + 3) * XSTRIDE + m] = v.w;
            }
        }
        __syncthreads();

        // ---- GEMM1: [n x 128] = x^T W1 ; thread tile M12 x N4, packed f32x2
        if (mg * 12 < n) {
            unsigned long long acc[6][4];   // [rowpair][col]
            #pragma unroll
            for (int r = 0; r < 6; r++)
                #pragma unroll
                for (int c = 0; c < 4; c++) acc[r][c] = 0ull;

            const float* xbase = &sm[XT_OFF + mg * 12];
            const float* wbase = &sm[W1S_OFF + ng * 4];
            #pragma unroll 4
            for (int k = 0; k < 128; k++) {
                const ulonglong2 xa = *(const ulonglong2*)(xbase + k * XSTRIDE);     // rows 0-3
                const ulonglong2 xb = *(const ulonglong2*)(xbase + k * XSTRIDE + 4); // rows 4-7
                const ulonglong2 xc = *(const ulonglong2*)(xbase + k * XSTRIDE + 8); // rows 8-11
                const float4 w = *(const float4*)(wbase + k * HID);
                const unsigned long long w0 = splat2(w.x), w1 = splat2(w.y),
                                         w2 = splat2(w.z), w3 = splat2(w.w);
                ffma2(acc[0][0], xa.x, w0); ffma2(acc[0][1], xa.x, w1);
                ffma2(acc[0][2], xa.x, w2); ffma2(acc[0][3], xa.x, w3);
                ffma2(acc[1][0], xa.y, w0); ffma2(acc[1][1], xa.y, w1);
                ffma2(acc[1][2], xa.y, w2); ffma2(acc[1][3], xa.y, w3);
                ffma2(acc[2][0], xb.x, w0); ffma2(acc[2][1], xb.x, w1);
                ffma2(acc[2][2], xb.x, w2); ffma2(acc[2][3], xb.x, w3);
                ffma2(acc[3][0], xb.y, w0); ffma2(acc[3][1], xb.y, w1);
                ffma2(acc[3][2], xb.y, w2); ffma2(acc[3][3], xb.y, w3);
                ffma2(acc[4][0], xc.x, w0); ffma2(acc[4][1], xc.x, w1);
                ffma2(acc[4][2], xc.x, w2); ffma2(acc[4][3], xc.x, w3);
                ffma2(acc[5][0], xc.y, w0); ffma2(acc[5][1], xc.y, w1);
                ffma2(acc[5][2], xc.y, w2); ffma2(acc[5][3], xc.y, w3);
            }
            // bias + exact GELU -> hT[col][m], 12 rows per thread
            #pragma unroll
            for (int c = 0; c < 4; c++) {
                const int col = ng * 4 + c;
                const float bb = sm[B1_OFF + col];
                float v[12];
                #pragma unroll
                for (int r = 0; r < 6; r++) {
                    const float2 p = unpack2(acc[r][c]);
                    v[2 * r]     = gelu_exact(p.x + bb);
                    v[2 * r + 1] = gelu_exact(p.y + bb);
                }
                float* hdst = &sm[HT_OFF + col * XSTRIDE + mg * 12];
                *(float4*)(hdst)     = make_float4(v[0], v[1], v[2],  v[3]);
                *(float4*)(hdst + 4) = make_float4(v[4], v[5], v[6],  v[7]);
                *(float4*)(hdst + 8) = make_float4(v[8], v[9], v[10], v[11]);
            }
        }
        __syncthreads();

        // ---- GEMM2: [n x 64] = h W2 ; thread tile M6 x N4, packed f32x2
        if (mg2 * 6 < n) {
            unsigned long long acc2[3][4];
            #pragma unroll
            for (int r = 0; r < 3; r++)
                #pragma unroll
                for (int c = 0; c < 4; c++) acc2[r][c] = 0ull;

            const float* hbase = &sm[HT_OFF + mg2 * 6];
            const float* wbase = &sm[W2S_OFF + ng2 * 4];
            #pragma unroll 4
            for (int k = 0; k < 128; k++) {
                const unsigned long long h0 = *(const unsigned long long*)(hbase + k * XSTRIDE);
                const unsigned long long h1 = *(const unsigned long long*)(hbase + k * XSTRIDE + 2);
                const unsigned long long h2 = *(const unsigned long long*)(hbase + k * XSTRIDE + 4);
                const float4 w = *(const float4*)(wbase + k * D);
                const unsigned long long w0 = splat2(w.x), w1 = splat2(w.y),
                                         w2 = splat2(w.z), w3 = splat2(w.w);
                ffma2(acc2[0][0], h0, w0); ffma2(acc2[0][1], h0, w1);
                ffma2(acc2[0][2], h0, w2); ffma2(acc2[0][3], h0, w3);
                ffma2(acc2[1][0], h1, w0); ffma2(acc2[1][1], h1, w1);
                ffma2(acc2[1][2], h1, w2); ffma2(acc2[1][3], h1, w3);
                ffma2(acc2[2][0], h2, w0); ffma2(acc2[2][1], h2, w1);
                ffma2(acc2[2][2], h2, w2); ffma2(acc2[2][3], h2, w3);
            }
            const float4 bb = *(const float4*)&sm[B2_OFF + ng2 * 4];
            float o[6][4];
            #pragma unroll
            for (int c = 0; c < 4; c++) {
                const float bc = (c == 0) ? bb.x : (c == 1) ? bb.y : (c == 2) ? bb.z : bb.w;
                const float2 p0 = unpack2(acc2[0][c]);
                const float2 p1 = unpack2(acc2[1][c]);
                const float2 p2 = unpack2(acc2[2][c]);
                o[0][c] = p0.x + bc; o[1][c] = p0.y + bc;
                o[2][c] = p1.x + bc; o[3][c] = p1.y + bc;
                o[4][c] = p2.x + bc; o[5][c] = p2.y + bc;
            }
            #pragma unroll
            for (int r = 0; r < 6; r++) {
                const int m = mg2 * 6 + r;
                if (m < n) {
                    const int it = items_sm[m];
                    float4 ov;
                    ov.x = o[r][0]; ov.y = o[r][1]; ov.z = o[r][2]; ov.w = o[r][3];
                    *(float4*)&buf[(size_t)it * D + ng2 * 4] = ov;
                }
            }
        }

        // ---- publish: buf writes -> fence -> flags (release)
        __threadfence();
        __syncthreads();
        if (tid < n) {
            const int it = items_sm[tid];
            *((volatile int*)&d_done[it]) = 1;
        }
        __syncthreads();   // smem reuse guard for next group
    }
}

// ---------------- host launcher -------------------------------------------
extern "C" void kernel_launch(void* const* d_in, const int* in_sizes, int n_in,
                              void* d_out, int out_size)
{
    const float* root = (const float*)d_in[0];   // [B, R, D]
    const float* W1   = (const float*)d_in[1];   // [T, 128, 128]
    const float* b1   = (const float*)d_in[2];   // [T, 128]
    const float* W2   = (const float*)d_in[3];   // [T, 128, 64]
    const float* b2   = (const float*)d_in[4];   // [T, 64]
    const int*   idx  = (const int*)d_in[5];     // [B, N, 2]
    const int*   typ  = (const int*)d_in[6];     // [B, N]
    float* out = (float*)d_out;                  // [B, N, D]

    static int configured = 0;
    if (!configured) {
        cudaFuncSetAttribute(k_compute, cudaFuncAttributeMaxDynamicSharedMemorySize, SMEM_BYTES);
        configured = 1;
    }

    k_init<<<256, 256>>>();
    k_levelize<<<B, 32>>>(idx, typ);
    k_segments<<<1, 256>>>();
    k_scatter<<<B, 256>>>(root, typ, out);
    k_compute<<<NCTA, 256, SMEM_BYTES>>>(W1, b1, W2, b2, idx, out);
}